// round 4
// baseline (speedup 1.0000x reference)
#include <cuda_runtime.h>

#define BB   2
#define CIN  256
#define CMID 64
#define CENC 100
#define HWHW 4096   // 64*64

// Scratch (allocation-free rule: __device__ globals)
__device__ float g_W1[BB * CMID * HWHW];        // conv1 output (b,64,64,64)
__device__ float g_W2[BB * CENC * HWHW];        // conv2 output (b,100,64,64)
__device__ float g_Wn[BB * HWHW * 4 * 28];      // softmaxed weights, [b][hl][wl][dydx][28(pad of 25)]

// ---------------------------------------------------------------------------
// K1: 1x1 conv (GEMM M=64 co, K=256 ci, N=4096 hw) + BN + ReLU
// tile: 64co x 32n per block, 256 threads, thread = 4co x 2n
// ---------------------------------------------------------------------------
__global__ __launch_bounds__(256) void k1_conv1x1(
    const float* __restrict__ X, const float* __restrict__ cw,
    const float* __restrict__ gamma, const float* __restrict__ beta,
    const float* __restrict__ mean, const float* __restrict__ var)
{
    __shared__ float As[32][65];   // [k][co], padded
    __shared__ float Bs[32][33];   // [k][n],  padded
    int b = blockIdx.y;
    int ncol0 = blockIdx.x * 32;
    int t = threadIdx.x;
    int co0 = (t & 15) * 4;
    int n0 = (t >> 4) * 2;
    const float* Xb = X + (size_t)b * CIN * HWHW;
    float acc[4][2] = {};
    for (int kc = 0; kc < CIN; kc += 32) {
        #pragma unroll
        for (int j = 0; j < 8; ++j) {
            int e = t + 256 * j;            // 2048 elems: [k][co]
            As[e & 31][e >> 5] = cw[(e >> 5) * CIN + kc + (e & 31)];
        }
        #pragma unroll
        for (int j = 0; j < 4; ++j) {
            int e = t + 256 * j;            // 1024 elems: [k][n]
            Bs[e >> 5][e & 31] = Xb[(size_t)(kc + (e >> 5)) * HWHW + ncol0 + (e & 31)];
        }
        __syncthreads();
        #pragma unroll
        for (int k = 0; k < 32; ++k) {
            float b0 = Bs[k][n0], b1 = Bs[k][n0 + 1];
            #pragma unroll
            for (int i = 0; i < 4; ++i) {
                float a = As[k][co0 + i];
                acc[i][0] += a * b0;
                acc[i][1] += a * b1;
            }
        }
        __syncthreads();
    }
    #pragma unroll
    for (int i = 0; i < 4; ++i) {
        int co = co0 + i;
        float sc = gamma[co] * rsqrtf(var[co] + 1e-5f);
        float sh = beta[co] - mean[co] * sc;
        #pragma unroll
        for (int j = 0; j < 2; ++j) {
            float v = acc[i][j] * sc + sh;
            g_W1[((size_t)b * CMID + co) * HWHW + ncol0 + n0 + j] = fmaxf(v, 0.f);
        }
    }
}

// ---------------------------------------------------------------------------
// K2: 3x3 conv (64ci -> 100co, pad 1) + BN (no relu)
// block: 16x16 spatial x 4 co, ci-chunks of 16 in smem. grid (16, 25, 2)
// ---------------------------------------------------------------------------
__global__ __launch_bounds__(256) void k2_conv3x3(
    const float* __restrict__ ew,
    const float* __restrict__ gamma, const float* __restrict__ beta,
    const float* __restrict__ mean, const float* __restrict__ var)
{
    __shared__ float Xs[16][18][18];
    __shared__ __align__(16) float Ws2[16][9][4];  // [ci][k][co]
    int b = blockIdx.z;
    int co0 = blockIdx.y * 4;
    int ty0 = (blockIdx.x >> 2) * 16;
    int tx0 = (blockIdx.x & 3) * 16;
    int t = threadIdx.x;
    int tx = t & 15, ty = t >> 4;
    float acc[4] = {};
    for (int cic = 0; cic < 4; ++cic) {
        for (int e = t; e < 16 * 324; e += 256) {
            int c = e / 324, rem = e % 324;
            int r = rem / 18, x = rem % 18;
            int y = ty0 + r - 1, xg = tx0 + x - 1;
            float v = 0.f;
            if (y >= 0 && y < 64 && xg >= 0 && xg < 64)
                v = g_W1[(((size_t)b * CMID + cic * 16 + c) * 64 + y) * 64 + xg];
            Xs[c][r][x] = v;
        }
        for (int e = t; e < 576; e += 256) {
            int co = e & 3, rem = e >> 2;
            int k = rem % 9, ci = rem / 9;
            Ws2[ci][k][co] = ew[(size_t)(co0 + co) * (CMID * 9) + (cic * 16 + ci) * 9 + k];
        }
        __syncthreads();
        for (int ci = 0; ci < 16; ++ci) {
            #pragma unroll
            for (int ky = 0; ky < 3; ++ky)
            #pragma unroll
            for (int kx = 0; kx < 3; ++kx) {
                float xv = Xs[ci][ty + ky][tx + kx];
                const float4 w4 = *(const float4*)&Ws2[ci][ky * 3 + kx][0];
                acc[0] += w4.x * xv; acc[1] += w4.y * xv;
                acc[2] += w4.z * xv; acc[3] += w4.w * xv;
            }
        }
        __syncthreads();
    }
    #pragma unroll
    for (int i = 0; i < 4; ++i) {
        int ch = co0 + i;
        float sc = gamma[ch] * rsqrtf(var[ch] + 1e-5f);
        float sh = beta[ch] - mean[ch] * sc;
        g_W2[(((size_t)b * CENC + ch) * 64 + ty0 + ty) * 64 + tx0 + tx] = acc[i] * sc + sh;
    }
}

// ---------------------------------------------------------------------------
// K3: pixel-shuffle + BN + clamp + pow + softmax over 25 taps
// thread = (b, hl, wl, dydx); writes 25 (pad 28) contiguous floats
// ---------------------------------------------------------------------------
__global__ __launch_bounds__(256) void k3_weights(
    const float* __restrict__ gamma, const float* __restrict__ beta,
    const float* __restrict__ mean, const float* __restrict__ var,
    const float* __restrict__ power_p)
{
    int idx = blockIdx.x * 256 + threadIdx.x;   // 32768 total
    int d = idx & 3;
    int rest = idx >> 2;                        // b*4096 + hl*64 + wl
    int wl = rest & 63, hl = (rest >> 6) & 63, b = rest >> 12;
    float p = fmaxf(power_p[0], 1e-5f);
    float v[25];
    float m = -1e30f;
    #pragma unroll
    for (int k = 0; k < 25; ++k) {
        int ch = k * 4 + d;                     // pixel-shuffle channel
        float sc = gamma[ch] * rsqrtf(var[ch] + 1e-5f);
        float sh = beta[ch] - mean[ch] * sc;
        float raw = g_W2[((size_t)b * CENC + ch) * HWHW + hl * 64 + wl];
        float x = fmaxf(raw * sc + sh, 1e-5f);
        x = __powf(x, p);
        v[k] = x;
        m = fmaxf(m, x);
    }
    float s = 0.f;
    #pragma unroll
    for (int k = 0; k < 25; ++k) { v[k] = __expf(v[k] - m); s += v[k]; }
    float inv = 1.f / s;
    float* o = g_Wn + ((size_t)rest * 4 + d) * 28;
    #pragma unroll
    for (int k = 0; k < 25; ++k) o[k] = v[k] * inv;
}

// ---------------------------------------------------------------------------
// K4: weighted 5x5 low-res gather -> 128x128 output
// block: 8x8 low-res tile x 4 subpixels (=256 thr), 32-channel chunk in smem
// grid (64 tiles, 8 ch-chunks, 2 b)
// ---------------------------------------------------------------------------
__global__ __launch_bounds__(256) void k4_gather(
    const float* __restrict__ X, float* __restrict__ out)
{
    __shared__ float Xs[32][12][12];
    int b = blockIdx.z;
    int c0 = blockIdx.y * 32;
    int ty0 = (blockIdx.x >> 3) * 8;
    int tx0 = (blockIdx.x & 7) * 8;
    int t = threadIdx.x;
    int d = t & 3;
    int sp = t >> 2;
    int sx = sp & 7, sy = sp >> 3;
    for (int e = t; e < 32 * 144; e += 256) {
        int c = e / 144, rem = e % 144;
        int r = rem / 12, x = rem % 12;
        int y = ty0 + r - 2, xg = tx0 + x - 2;
        float v = 0.f;
        if (y >= 0 && y < 64 && xg >= 0 && xg < 64)
            v = X[(((size_t)b * CIN + c0 + c) * 64 + y) * 64 + xg];
        Xs[c][r][x] = v;
    }
    int hl = ty0 + sy, wl = tx0 + sx;
    const float4* wp = (const float4*)(g_Wn + (((size_t)b * HWHW + hl * 64 + wl) * 4 + d) * 28);
    float w[28];
    #pragma unroll
    for (int q = 0; q < 7; ++q) {
        float4 w4 = wp[q];
        w[q * 4] = w4.x; w[q * 4 + 1] = w4.y; w[q * 4 + 2] = w4.z; w[q * 4 + 3] = w4.w;
    }
    __syncthreads();
    int dy = d >> 1, dx = d & 1;
    int h_ = 2 * hl + dy, w_ = 2 * wl + dx;
    float* ob = out + (((size_t)b * CIN + c0) * 128 + h_) * 128 + w_;
    #pragma unroll 1
    for (int cc = 0; cc < 32; cc += 4) {
        float a0 = 0.f, a1 = 0.f, a2 = 0.f, a3 = 0.f;
        #pragma unroll
        for (int k = 0; k < 25; ++k) {
            int ki = k / 5, kj = k % 5;
            float wv = w[k];
            a0 += wv * Xs[cc    ][sy + ki][sx + kj];
            a1 += wv * Xs[cc + 1][sy + ki][sx + kj];
            a2 += wv * Xs[cc + 2][sy + ki][sx + kj];
            a3 += wv * Xs[cc + 3][sy + ki][sx + kj];
        }
        ob[(size_t)(cc    ) * 16384] = a0;
        ob[(size_t)(cc + 1) * 16384] = a1;
        ob[(size_t)(cc + 2) * 16384] = a2;
        ob[(size_t)(cc + 3) * 16384] = a3;
    }
}

// ---------------------------------------------------------------------------
extern "C" void kernel_launch(void* const* d_in, const int* in_sizes, int n_in,
                              void* d_out, int out_size)
{
    const float* X          = (const float*)d_in[0];
    const float* comp_w     = (const float*)d_in[1];
    const float* comp_gamma = (const float*)d_in[2];
    const float* comp_beta  = (const float*)d_in[3];
    const float* comp_mean  = (const float*)d_in[4];
    const float* comp_var   = (const float*)d_in[5];
    const float* enc_w      = (const float*)d_in[6];
    const float* enc_gamma  = (const float*)d_in[7];
    const float* enc_beta   = (const float*)d_in[8];
    const float* enc_mean   = (const float*)d_in[9];
    const float* enc_var    = (const float*)d_in[10];
    const float* power_p    = (const float*)d_in[11];
    float* out = (float*)d_out;

    k1_conv1x1<<<dim3(128, 2), 256>>>(X, comp_w, comp_gamma, comp_beta,
                                      comp_mean, comp_var);
    k2_conv3x3<<<dim3(16, 25, 2), 256>>>(enc_w, enc_gamma, enc_beta,
                                         enc_mean, enc_var);
    k3_weights<<<128, 256>>>(enc_gamma, enc_beta, enc_mean, enc_var, power_p);
    k4_gather<<<dim3(64, 8, 2), 256>>>(X, out);
}

// round 6
// speedup vs baseline: 1.4232x; 1.4232x over previous
#include <cuda_runtime.h>

#define BB   2
#define CIN  256
#define CMID 64
#define CENC 100
#define HWHW 4096   // 64*64

// Scratch (allocation-free rule: __device__ globals)
__device__ float g_W1[BB * CMID * HWHW];        // conv1 output (b,64,64,64)
__device__ float g_W2[BB * CENC * HWHW];        // conv2 output (b,100,64,64)
__device__ float g_Wn[BB * HWHW * 100];         // softmaxed weights, [b][pix][k(25)][d(4)]

// ---------------------------------------------------------------------------
// K1: 1x1 conv (GEMM M=64co x K=256ci x N=4096hw) + BN + ReLU
// block: 64co x 64n, 256 threads, thread = 4co x 4n, k-chunk 16
// ---------------------------------------------------------------------------
__global__ __launch_bounds__(256) void k1_conv1x1(
    const float* __restrict__ X, const float* __restrict__ cw,
    const float* __restrict__ gamma, const float* __restrict__ beta,
    const float* __restrict__ mean, const float* __restrict__ var)
{
    __shared__ __align__(16) float As[16][68];   // [k][co]
    __shared__ __align__(16) float Bs[16][68];   // [k][n]
    int b = blockIdx.y;
    int n_base = blockIdx.x * 64;
    int t = threadIdx.x;
    int co0 = (t & 15) * 4;
    int n0  = (t >> 4) * 4;
    const float* Xb = X + (size_t)b * CIN * HWHW;
    float acc[4][4] = {};
    for (int kc = 0; kc < CIN; kc += 16) {
        {   // A: cw[co][ci] -> As[k][co]   (transpose on store)
            int co = t >> 2, kk = (t & 3) * 4;
            float4 a4 = *(const float4*)&cw[(size_t)co * CIN + kc + kk];
            As[kk + 0][co] = a4.x; As[kk + 1][co] = a4.y;
            As[kk + 2][co] = a4.z; As[kk + 3][co] = a4.w;
        }
        {   // B: X[k][n] -> Bs[k][n]
            int kk = t >> 4, nn = (t & 15) * 4;
            float4 b4 = *(const float4*)&Xb[(size_t)(kc + kk) * HWHW + n_base + nn];
            *(float4*)&Bs[kk][nn] = b4;
        }
        __syncthreads();
        #pragma unroll
        for (int k = 0; k < 16; ++k) {
            float4 a4 = *(const float4*)&As[k][co0];
            float4 b4 = *(const float4*)&Bs[k][n0];
            float av[4] = {a4.x, a4.y, a4.z, a4.w};
            float bv[4] = {b4.x, b4.y, b4.z, b4.w};
            #pragma unroll
            for (int i = 0; i < 4; ++i)
                #pragma unroll
                for (int j = 0; j < 4; ++j)
                    acc[i][j] += av[i] * bv[j];
        }
        __syncthreads();
    }
    #pragma unroll
    for (int i = 0; i < 4; ++i) {
        int co = co0 + i;
        float sc = gamma[co] * rsqrtf(var[co] + 1e-5f);
        float sh = beta[co] - mean[co] * sc;
        float4 v;
        v.x = fmaxf(acc[i][0] * sc + sh, 0.f);
        v.y = fmaxf(acc[i][1] * sc + sh, 0.f);
        v.z = fmaxf(acc[i][2] * sc + sh, 0.f);
        v.w = fmaxf(acc[i][3] * sc + sh, 0.f);
        *(float4*)&g_W1[((size_t)b * CMID + co) * HWHW + n_base + n0] = v;
    }
}

// ---------------------------------------------------------------------------
// K2: 3x3 conv (64ci -> 100co, pad 1) + BN (no relu)
// block: 32x16 spatial tile, 256 thr, thread = 2 pixels (ty, ty+8) x 4 co
// grid (8 tiles, 25 co-groups, 2 b); ci-chunks of 16 in smem
// ---------------------------------------------------------------------------
__global__ __launch_bounds__(256) void k2_conv3x3(
    const float* __restrict__ ew,
    const float* __restrict__ gamma, const float* __restrict__ beta,
    const float* __restrict__ mean, const float* __restrict__ var)
{
    __shared__ float Xs[16][18][36];               // [ci][row][col], 34 used
    __shared__ __align__(16) float Ws2[16][9][4];  // [ci][k][co]
    int b = blockIdx.z;
    int co0 = blockIdx.y * 4;
    int ty0 = (blockIdx.x >> 1) * 16;
    int tx0 = (blockIdx.x & 1) * 32;
    int t = threadIdx.x;
    int tx = t & 31, ty = t >> 5;                  // ty in 0..7, 2 rows/thread
    float acc0[4] = {}, acc1[4] = {};
    for (int cic = 0; cic < 4; ++cic) {
        for (int e = t; e < 16 * 18 * 34; e += 256) {
            int c = e / 612, rem = e % 612;
            int r = rem / 34, x = rem % 34;
            int y = ty0 + r - 1, xg = tx0 + x - 1;
            float v = 0.f;
            if (y >= 0 && y < 64 && xg >= 0 && xg < 64)
                v = g_W1[(((size_t)b * CMID + cic * 16 + c) * 64 + y) * 64 + xg];
            Xs[c][r][x] = v;
        }
        for (int e = t; e < 576; e += 256) {
            int co = e & 3, rem = e >> 2;
            int k = rem % 9, ci = rem / 9;
            Ws2[ci][k][co] = ew[(size_t)(co0 + co) * (CMID * 9) + (cic * 16 + ci) * 9 + k];
        }
        __syncthreads();
        for (int ci = 0; ci < 16; ++ci) {
            #pragma unroll
            for (int ky = 0; ky < 3; ++ky)
            #pragma unroll
            for (int kx = 0; kx < 3; ++kx) {
                float xv0 = Xs[ci][ty + ky][tx + kx];
                float xv1 = Xs[ci][ty + 8 + ky][tx + kx];
                const float4 w4 = *(const float4*)&Ws2[ci][ky * 3 + kx][0];
                acc0[0] += w4.x * xv0; acc0[1] += w4.y * xv0;
                acc0[2] += w4.z * xv0; acc0[3] += w4.w * xv0;
                acc1[0] += w4.x * xv1; acc1[1] += w4.y * xv1;
                acc1[2] += w4.z * xv1; acc1[3] += w4.w * xv1;
            }
        }
        __syncthreads();
    }
    #pragma unroll
    for (int i = 0; i < 4; ++i) {
        int ch = co0 + i;
        float sc = gamma[ch] * rsqrtf(var[ch] + 1e-5f);
        float sh = beta[ch] - mean[ch] * sc;
        size_t base = ((size_t)b * CENC + ch) * 64;
        g_W2[(base + ty0 + ty) * 64 + tx0 + tx]     = acc0[i] * sc + sh;
        g_W2[(base + ty0 + ty + 8) * 64 + tx0 + tx] = acc1[i] * sc + sh;
    }
}

// ---------------------------------------------------------------------------
// K3: pixel-shuffle + clamp + pow + softmax over 25 taps (BN already in K2)
// thread = (b, pixel, dydx); writes v[k] to g_Wn[b][pix][k*4 + d]
// ---------------------------------------------------------------------------
__global__ __launch_bounds__(256) void k3_weights(const float* __restrict__ power_p)
{
    int idx = blockIdx.x * 256 + threadIdx.x;   // 32768 total
    int d = idx & 3;
    int rest = idx >> 2;                        // b*4096 + hl*64 + wl
    int pix = rest & 4095, b = rest >> 12;
    float p = fmaxf(power_p[0], 1e-5f);
    float v[25];
    float m = -1e30f;
    #pragma unroll
    for (int k = 0; k < 25; ++k) {
        int ch = k * 4 + d;                     // pixel-shuffle channel
        float raw = g_W2[((size_t)b * CENC + ch) * HWHW + pix];
        float x = fmaxf(raw, 1e-5f);
        x = __powf(x, p);
        v[k] = x;
        m = fmaxf(m, x);
    }
    float s = 0.f;
    #pragma unroll
    for (int k = 0; k < 25; ++k) { v[k] = __expf(v[k] - m); s += v[k]; }
    float inv = 1.f / s;
    float* o = g_Wn + (size_t)rest * 100;
    #pragma unroll
    for (int k = 0; k < 25; ++k) o[k * 4 + d] = v[k] * inv;
}

// ---------------------------------------------------------------------------
// K4: weighted 5x5 low-res gather -> 128x128 output
// block: 8x8 low-res tile x 32 channels, 256 thr = 64 spatial x 4 ch-quads
// thread computes 4 subpixels x 8 channels; X channel-fastest in smem,
// weights [pix][tap][4 subpix] staged in smem -> per tap: 3 LDS.128 + 32 FFMA
// grid (64 tiles, 8 ch-chunks, 2 b)
// ---------------------------------------------------------------------------
__global__ __launch_bounds__(256) void k4_gather(
    const float* __restrict__ X, float* __restrict__ out)
{
    __shared__ __align__(16) float Xs[12][12][36];  // [r][x][c], 32 ch used
    __shared__ __align__(16) float Ws[64][25][4];   // [pix][tap][subpix]
    int b = blockIdx.z;
    int c0 = blockIdx.y * 32;
    int ty0 = (blockIdx.x >> 3) * 8;
    int tx0 = (blockIdx.x & 7) * 8;
    int t = threadIdx.x;
    int sp = t & 63;                 // spatial fastest (warp = 32 spatials)
    int j  = t >> 6;                 // channel quad 0..3
    int sx = sp & 7, sy = sp >> 3;

    // stage X tile (10x10 core + halo2 = 12x12) x 32 ch, channel-fastest
    for (int e = t; e < 32 * 144; e += 256) {
        int c = e / 144, rem = e % 144;
        int r = rem / 12, x = rem % 12;
        int y = ty0 + r - 2, xg = tx0 + x - 2;
        float v = 0.f;
        if (y >= 0 && y < 64 && xg >= 0 && xg < 64)
            v = X[(((size_t)b * CIN + c0 + c) * 64 + y) * 64 + xg];
        Xs[r][x][c] = v;
    }
    // stage weights: 64 px * 25 float4
    {
        const float4* wg = (const float4*)(g_Wn + ((size_t)b * HWHW + ty0 * 64 + tx0) * 100);
        float4* wsm = (float4*)&Ws[0][0][0];
        for (int e = t; e < 64 * 25; e += 256) {
            int p = e / 25, i = e % 25;
            int py = p >> 3, px = p & 7;
            wsm[e] = wg[((size_t)py * 64 + px) * 25 + i];
        }
    }
    __syncthreads();

    float a0[4][4] = {};   // [ch][subpix] channels j*4..+3
    float a1[4][4] = {};   // channels 16+j*4..+3
    int clo = j * 4, chi = 16 + j * 4;
    #pragma unroll
    for (int k = 0; k < 25; ++k) {
        int ki = k / 5, kj = k % 5;
        float4 w4 = *(const float4*)&Ws[sp][k][0];
        float wv[4] = {w4.x, w4.y, w4.z, w4.w};
        float4 x0 = *(const float4*)&Xs[sy + ki][sx + kj][clo];
        float4 x1 = *(const float4*)&Xs[sy + ki][sx + kj][chi];
        float xv0[4] = {x0.x, x0.y, x0.z, x0.w};
        float xv1[4] = {x1.x, x1.y, x1.z, x1.w};
        #pragma unroll
        for (int i = 0; i < 4; ++i)
            #pragma unroll
            for (int dd = 0; dd < 4; ++dd) {
                a0[i][dd] += wv[dd] * xv0[i];
                a1[i][dd] += wv[dd] * xv1[i];
            }
    }

    // store: subpix d = dy*2+dx ; float2 over dx (w_ even-aligned)
    int hl = ty0 + sy, wl = tx0 + sx;
    int w_ = 2 * wl;
    #pragma unroll
    for (int i = 0; i < 4; ++i) {
        {   // chunk 0
            size_t cb = (((size_t)b * CIN + c0 + clo + i) * 128) * 128;
            *(float2*)&out[cb + (size_t)(2 * hl)     * 128 + w_] = make_float2(a0[i][0], a0[i][1]);
            *(float2*)&out[cb + (size_t)(2 * hl + 1) * 128 + w_] = make_float2(a0[i][2], a0[i][3]);
        }
        {   // chunk 1
            size_t cb = (((size_t)b * CIN + c0 + chi + i) * 128) * 128;
            *(float2*)&out[cb + (size_t)(2 * hl)     * 128 + w_] = make_float2(a1[i][0], a1[i][1]);
            *(float2*)&out[cb + (size_t)(2 * hl + 1) * 128 + w_] = make_float2(a1[i][2], a1[i][3]);
        }
    }
}

// ---------------------------------------------------------------------------
extern "C" void kernel_launch(void* const* d_in, const int* in_sizes, int n_in,
                              void* d_out, int out_size)
{
    const float* X          = (const float*)d_in[0];
    const float* comp_w     = (const float*)d_in[1];
    const float* comp_gamma = (const float*)d_in[2];
    const float* comp_beta  = (const float*)d_in[3];
    const float* comp_mean  = (const float*)d_in[4];
    const float* comp_var   = (const float*)d_in[5];
    const float* enc_w      = (const float*)d_in[6];
    const float* enc_gamma  = (const float*)d_in[7];
    const float* enc_beta   = (const float*)d_in[8];
    const float* enc_mean   = (const float*)d_in[9];
    const float* enc_var    = (const float*)d_in[10];
    const float* power_p    = (const float*)d_in[11];
    float* out = (float*)d_out;

    k1_conv1x1<<<dim3(64, 2), 256>>>(X, comp_w, comp_gamma, comp_beta,
                                     comp_mean, comp_var);
    k2_conv3x3<<<dim3(8, 25, 2), 256>>>(enc_w, enc_gamma, enc_beta,
                                        enc_mean, enc_var);
    k3_weights<<<128, 256>>>(power_p);
    k4_gather<<<dim3(64, 8, 2), 256>>>(X, out);
}

// round 8
// speedup vs baseline: 1.6421x; 1.1538x over previous
#include <cuda_runtime.h>

#define BB   2
#define CIN  256
#define CMID 64
#define CENC 100
#define HWHW 4096   // 64*64

// Scratch (allocation-free rule: __device__ globals)
__device__ float g_W1[BB * CMID * HWHW];        // conv1 output (b,64,64,64)
__device__ float g_W2[BB * CENC * HWHW];        // conv2 output (b,100,64,64)
// softmaxed weights permuted to k4's tile order: [b][tile(64)][within(64)][k(25)][d(4)]
__device__ float g_Wn[BB * 64 * 64 * 100];

// ---------------------------------------------------------------------------
// K1: 1x1 conv (GEMM M=64co x K=256ci x N=4096hw) + BN + ReLU
// block: 64co x 64n, 256 threads, thread = 4co x 4n, k-chunk 16
// ---------------------------------------------------------------------------
__global__ __launch_bounds__(256) void k1_conv1x1(
    const float* __restrict__ X, const float* __restrict__ cw,
    const float* __restrict__ gamma, const float* __restrict__ beta,
    const float* __restrict__ mean, const float* __restrict__ var)
{
    __shared__ __align__(16) float As[16][68];   // [k][co]
    __shared__ __align__(16) float Bs[16][68];   // [k][n]
    int b = blockIdx.y;
    int n_base = blockIdx.x * 64;
    int t = threadIdx.x;
    int co0 = (t & 15) * 4;
    int n0  = (t >> 4) * 4;
    const float* Xb = X + (size_t)b * CIN * HWHW;
    float acc[4][4] = {};
    for (int kc = 0; kc < CIN; kc += 16) {
        {   // A: cw[co][ci] -> As[k][co]   (transpose on store)
            int co = t >> 2, kk = (t & 3) * 4;
            float4 a4 = *(const float4*)&cw[(size_t)co * CIN + kc + kk];
            As[kk + 0][co] = a4.x; As[kk + 1][co] = a4.y;
            As[kk + 2][co] = a4.z; As[kk + 3][co] = a4.w;
        }
        {   // B: X[k][n] -> Bs[k][n]
            int kk = t >> 4, nn = (t & 15) * 4;
            float4 b4 = *(const float4*)&Xb[(size_t)(kc + kk) * HWHW + n_base + nn];
            *(float4*)&Bs[kk][nn] = b4;
        }
        __syncthreads();
        #pragma unroll
        for (int k = 0; k < 16; ++k) {
            float4 a4 = *(const float4*)&As[k][co0];
            float4 b4 = *(const float4*)&Bs[k][n0];
            float av[4] = {a4.x, a4.y, a4.z, a4.w};
            float bv[4] = {b4.x, b4.y, b4.z, b4.w};
            #pragma unroll
            for (int i = 0; i < 4; ++i)
                #pragma unroll
                for (int j = 0; j < 4; ++j)
                    acc[i][j] += av[i] * bv[j];
        }
        __syncthreads();
    }
    #pragma unroll
    for (int i = 0; i < 4; ++i) {
        int co = co0 + i;
        float sc = gamma[co] * rsqrtf(var[co] + 1e-5f);
        float sh = beta[co] - mean[co] * sc;
        float4 v;
        v.x = fmaxf(acc[i][0] * sc + sh, 0.f);
        v.y = fmaxf(acc[i][1] * sc + sh, 0.f);
        v.z = fmaxf(acc[i][2] * sc + sh, 0.f);
        v.w = fmaxf(acc[i][3] * sc + sh, 0.f);
        *(float4*)&g_W1[((size_t)b * CMID + co) * HWHW + n_base + n0] = v;
    }
}

// ---------------------------------------------------------------------------
// K2: 3x3 conv (64ci -> 100co, pad 1) + BN (no relu)
// block: 32x16 spatial tile, 256 thr, thread = 2 pixels (ty, ty+8) x 4 co
// grid (8 tiles, 25 co-groups, 2 b); ci-chunks of 16 in smem
// Staging strength-reduced: thread = (ci, col-lane), row loop with ptr bump.
// ---------------------------------------------------------------------------
__global__ __launch_bounds__(256) void k2_conv3x3(
    const float* __restrict__ ew,
    const float* __restrict__ gamma, const float* __restrict__ beta,
    const float* __restrict__ mean, const float* __restrict__ var)
{
    __shared__ float Xs[16][18][36];               // [ci][row][col], 34 used
    __shared__ __align__(16) float Ws2[16][9][4];  // [ci][k][co]
    int b = blockIdx.z;
    int co0 = blockIdx.y * 4;
    int ty0 = (blockIdx.x >> 1) * 16;
    int tx0 = (blockIdx.x & 1) * 32;
    int t = threadIdx.x;
    int tx = t & 31, ty = t >> 5;                  // ty in 0..7, 2 rows/thread

    // staging thread map (fixed per thread, computed once)
    int sc_ = t >> 4;          // ci lane 0..15
    int sq  = t & 15;          // col lane 0..15 -> cols sq, sq+16, (sq+32 if sq<2)
    int xg1 = tx0 + sq - 1;
    int xg2 = tx0 + sq + 15;
    int xg3 = tx0 + sq + 31;
    bool okx1 = (xg1 >= 0) && (xg1 < 64);
    bool okx2 = (xg2 < 64);                       // xg2 >= 15 always
    bool okx3 = (sq < 2) && (xg3 < 64);

    float acc0[4] = {}, acc1[4] = {};
    for (int cic = 0; cic < 4; ++cic) {
        {   // X stage: rows 18, thread owns (ci=sc_, cols sq/sq+16/sq+32)
            const float* basec = g_W1 +
                (((size_t)b * CMID + cic * 16 + sc_) * 64) * 64;
            #pragma unroll 3
            for (int r = 0; r < 18; ++r) {
                int y = ty0 + r - 1;
                bool oky = (y >= 0) && (y < 64);
                const float* src = basec + (size_t)y * 64;
                float v1 = 0.f, v2 = 0.f, v3 = 0.f;
                if (oky) {
                    if (okx1) v1 = src[xg1];
                    if (okx2) v2 = src[xg2];
                    if (okx3) v3 = src[xg3];
                }
                float* dst = &Xs[sc_][r][0];
                dst[sq] = v1;
                dst[sq + 16] = v2;
                if (sq < 2) dst[sq + 32] = v3;
            }
        }
        for (int e = t; e < 576; e += 256) {
            int co = e & 3, rem = e >> 2;
            int k = rem % 9, ci = rem / 9;
            Ws2[ci][k][co] = ew[(size_t)(co0 + co) * (CMID * 9) + (cic * 16 + ci) * 9 + k];
        }
        __syncthreads();
        for (int ci = 0; ci < 16; ++ci) {
            #pragma unroll
            for (int ky = 0; ky < 3; ++ky)
            #pragma unroll
            for (int kx = 0; kx < 3; ++kx) {
                float xv0 = Xs[ci][ty + ky][tx + kx];
                float xv1 = Xs[ci][ty + 8 + ky][tx + kx];
                const float4 w4 = *(const float4*)&Ws2[ci][ky * 3 + kx][0];
                acc0[0] += w4.x * xv0; acc0[1] += w4.y * xv0;
                acc0[2] += w4.z * xv0; acc0[3] += w4.w * xv0;
                acc1[0] += w4.x * xv1; acc1[1] += w4.y * xv1;
                acc1[2] += w4.z * xv1; acc1[3] += w4.w * xv1;
            }
        }
        __syncthreads();
    }
    #pragma unroll
    for (int i = 0; i < 4; ++i) {
        int ch = co0 + i;
        float sc = gamma[ch] * rsqrtf(var[ch] + 1e-5f);
        float sh = beta[ch] - mean[ch] * sc;
        size_t base = ((size_t)b * CENC + ch) * 64;
        g_W2[(base + ty0 + ty) * 64 + tx0 + tx]     = acc0[i] * sc + sh;
        g_W2[(base + ty0 + ty + 8) * 64 + tx0 + tx] = acc1[i] * sc + sh;
    }
}

// ---------------------------------------------------------------------------
// K3: pixel-shuffle + clamp + pow + softmax over 25 taps (BN already in K2)
// thread = (b, pixel, dydx); writes into k4-tile-permuted g_Wn
// ---------------------------------------------------------------------------
__global__ __launch_bounds__(256) void k3_weights(const float* __restrict__ power_p)
{
    int idx = blockIdx.x * 256 + threadIdx.x;   // 32768 total
    int d = idx & 3;
    int rest = idx >> 2;                        // b*4096 + hl*64 + wl
    int pix = rest & 4095, b = rest >> 12;
    int hl = pix >> 6, wl = pix & 63;
    float p = fmaxf(power_p[0], 1e-5f);
    float v[25];
    float m = -1e30f;
    #pragma unroll
    for (int k = 0; k < 25; ++k) {
        int ch = k * 4 + d;                     // pixel-shuffle channel
        float raw = g_W2[((size_t)b * CENC + ch) * HWHW + pix];
        float x = fmaxf(raw, 1e-5f);
        x = __powf(x, p);
        v[k] = x;
        m = fmaxf(m, x);
    }
    float s = 0.f;
    #pragma unroll
    for (int k = 0; k < 25; ++k) { v[k] = __expf(v[k] - m); s += v[k]; }
    float inv = 1.f / s;
    // permuted output: [b][tile][within][k][d]
    int tile   = ((hl >> 3) << 3) + (wl >> 3);
    int within = ((hl & 7) << 3) + (wl & 7);
    float* o = g_Wn + (((size_t)b * 64 + tile) * 64 + within) * 100;
    #pragma unroll
    for (int k = 0; k < 25; ++k) o[k * 4 + d] = v[k] * inv;
}

// ---------------------------------------------------------------------------
// K4: weighted 5x5 low-res gather -> 128x128 output
// block: 8x8 low-res tile x 32 channels, 256 thr = 64 spatial x 4 ch-quads
// per tap: 1 LDS.128 (w) + 2 LDS.128 (X) + 32 FFMA.
// Weight stage = pure linear float4 copy (g_Wn pre-permuted by k3).
// X stage: thread<144 owns fixed (r,x), ptr-bump over 32 channels.
// grid (64 tiles, 8 ch-chunks, 2 b)
// ---------------------------------------------------------------------------
__global__ __launch_bounds__(256) void k4_gather(
    const float* __restrict__ X, float* __restrict__ out)
{
    __shared__ __align__(16) float Xs[12][12][36];  // [r][x][c], 32 ch used
    __shared__ __align__(16) float Ws[64][25][4];   // [within][tap][subpix]
    int b = blockIdx.z;
    int c0 = blockIdx.y * 32;
    int tile = blockIdx.x;
    int ty0 = (tile >> 3) * 8;
    int tx0 = (tile & 7) * 8;
    int t = threadIdx.x;
    int sp = t & 63;                 // spatial fastest (warp = 32 spatials)
    int j  = t >> 6;                 // channel quad 0..3
    int sx = sp & 7, sy = sp >> 3;

    // weights: linear copy of 1600 float4 (already in this block's order)
    {
        const float4* wg4 = (const float4*)g_Wn + ((size_t)b * 64 + tile) * 1600;
        float4* wsm = (float4*)&Ws[0][0][0];
        #pragma unroll
        for (int e = t; e < 1600; e += 256) wsm[e] = wg4[e];
    }
    // X tile: threads 0..143 own one (r,x), loop 32 channels with ptr bump
    if (t < 144) {
        int r = t / 12, x = t % 12;
        int y = ty0 + r - 2, xg = tx0 + x - 2;
        bool ok = (y >= 0) && (y < 64) && (xg >= 0) && (xg < 64);
        const float* src = X + (((size_t)b * CIN + c0) * 64 + y) * 64 + xg;
        float* dst = &Xs[r][x][0];
        #pragma unroll 4
        for (int c = 0; c < 32; ++c) {
            float v = 0.f;
            if (ok) v = src[(size_t)c * HWHW];
            dst[c] = v;
        }
    }
    __syncthreads();

    float a0[4][4] = {};   // [ch][subpix] channels j*4..+3
    float a1[4][4] = {};   // channels 16+j*4..+3
    int clo = j * 4, chi = 16 + j * 4;
    #pragma unroll
    for (int k = 0; k < 25; ++k) {
        int ki = k / 5, kj = k % 5;
        float4 w4 = *(const float4*)&Ws[sp][k][0];
        float wv[4] = {w4.x, w4.y, w4.z, w4.w};
        float4 x0 = *(const float4*)&Xs[sy + ki][sx + kj][clo];
        float4 x1 = *(const float4*)&Xs[sy + ki][sx + kj][chi];
        float xv0[4] = {x0.x, x0.y, x0.z, x0.w};
        float xv1[4] = {x1.x, x1.y, x1.z, x1.w};
        #pragma unroll
        for (int i = 0; i < 4; ++i)
            #pragma unroll
            for (int dd = 0; dd < 4; ++dd) {
                a0[i][dd] += wv[dd] * xv0[i];
                a1[i][dd] += wv[dd] * xv1[i];
            }
    }

    // store: subpix d = dy*2+dx ; float2 over dx (w_ even-aligned)
    int hl = ty0 + sy, wl = tx0 + sx;
    int w_ = 2 * wl;
    #pragma unroll
    for (int i = 0; i < 4; ++i) {
        {   // chunk 0
            size_t cb = (((size_t)b * CIN + c0 + clo + i) * 128) * 128;
            *(float2*)&out[cb + (size_t)(2 * hl)     * 128 + w_] = make_float2(a0[i][0], a0[i][1]);
            *(float2*)&out[cb + (size_t)(2 * hl + 1) * 128 + w_] = make_float2(a0[i][2], a0[i][3]);
        }
        {   // chunk 1
            size_t cb = (((size_t)b * CIN + c0 + chi + i) * 128) * 128;
            *(float2*)&out[cb + (size_t)(2 * hl)     * 128 + w_] = make_float2(a1[i][0], a1[i][1]);
            *(float2*)&out[cb + (size_t)(2 * hl + 1) * 128 + w_] = make_float2(a1[i][2], a1[i][3]);
        }
    }
}

// ---------------------------------------------------------------------------
extern "C" void kernel_launch(void* const* d_in, const int* in_sizes, int n_in,
                              void* d_out, int out_size)
{
    const float* X          = (const float*)d_in[0];
    const float* comp_w     = (const float*)d_in[1];
    const float* comp_gamma = (const float*)d_in[2];
    const float* comp_beta  = (const float*)d_in[3];
    const float* comp_mean  = (const float*)d_in[4];
    const float* comp_var   = (const float*)d_in[5];
    const float* enc_w      = (const float*)d_in[6];
    const float* enc_gamma  = (const float*)d_in[7];
    const float* enc_beta   = (const float*)d_in[8];
    const float* enc_mean   = (const float*)d_in[9];
    const float* enc_var    = (const float*)d_in[10];
    const float* power_p    = (const float*)d_in[11];
    float* out = (float*)d_out;

    k1_conv1x1<<<dim3(64, 2), 256>>>(X, comp_w, comp_gamma, comp_beta,
                                     comp_mean, comp_var);
    k2_conv3x3<<<dim3(8, 25, 2), 256>>>(enc_w, enc_gamma, enc_beta,
                                        enc_mean, enc_var);
    k3_weights<<<128, 256>>>(power_p);
    k4_gather<<<dim3(64, 8, 2), 256>>>(X, out);
}

// round 10
// speedup vs baseline: 1.7037x; 1.0375x over previous
#include <cuda_runtime.h>

#define BB   2
#define CIN  256
#define CMID 64
#define CENC 100
#define HWHW 4096   // 64*64

typedef unsigned long long u64;

// ---- packed fp32x2 helpers (FFMA2: one instr = two fp32 FMAs, full precision)
__device__ __forceinline__ u64 dup2(float v) {
    u64 r; asm("mov.b64 %0, {%1,%1};" : "=l"(r) : "f"(v)); return r;
}
__device__ __forceinline__ void fma2(u64& d, u64 a, u64 b) {
    asm("fma.rn.f32x2 %0, %1, %2, %0;" : "+l"(d) : "l"(a), "l"(b));
}
__device__ __forceinline__ float2 unpack2(u64 v) {
    float2 f; asm("mov.b64 {%0,%1}, %2;" : "=f"(f.x), "=f"(f.y) : "l"(v)); return f;
}

// Scratch (allocation-free rule: __device__ globals)
__device__ float g_W1[BB * CMID * HWHW];        // conv1 output (b,64,64,64)
__device__ float g_W2[BB * CENC * HWHW];        // conv2 output (b,100,64,64)
// softmaxed weights permuted to k4's tile order: [b][tile(64)][within(64)][k(25)][d(4)]
__device__ float g_Wn[BB * 64 * 64 * 100];

// ---------------------------------------------------------------------------
// K1: 1x1 conv (GEMM M=64co x K=256ci x N=4096hw) + BN + ReLU
// block: 64co x 64n, 256 threads, thread = 4co x 4n (as 2 n-pairs), k-chunk 16
// ---------------------------------------------------------------------------
__global__ __launch_bounds__(256) void k1_conv1x1(
    const float* __restrict__ X, const float* __restrict__ cw,
    const float* __restrict__ gamma, const float* __restrict__ beta,
    const float* __restrict__ mean, const float* __restrict__ var)
{
    __shared__ __align__(16) float As[16][68];   // [k][co]
    __shared__ __align__(16) float Bs[16][68];   // [k][n]
    int b = blockIdx.y;
    int n_base = blockIdx.x * 64;
    int t = threadIdx.x;
    int co0 = (t & 15) * 4;
    int n0  = (t >> 4) * 4;
    const float* Xb = X + (size_t)b * CIN * HWHW;
    u64 acc[4][2];
    #pragma unroll
    for (int i = 0; i < 4; ++i) { acc[i][0] = 0ULL; acc[i][1] = 0ULL; }
    for (int kc = 0; kc < CIN; kc += 16) {
        {   // A: cw[co][ci] -> As[k][co]   (transpose on store)
            int co = t >> 2, kk = (t & 3) * 4;
            float4 a4 = *(const float4*)&cw[(size_t)co * CIN + kc + kk];
            As[kk + 0][co] = a4.x; As[kk + 1][co] = a4.y;
            As[kk + 2][co] = a4.z; As[kk + 3][co] = a4.w;
        }
        {   // B: X[k][n] -> Bs[k][n]
            int kk = t >> 4, nn = (t & 15) * 4;
            float4 b4 = *(const float4*)&Xb[(size_t)(kc + kk) * HWHW + n_base + nn];
            *(float4*)&Bs[kk][nn] = b4;
        }
        __syncthreads();
        #pragma unroll
        for (int k = 0; k < 16; ++k) {
            float4 a4 = *(const float4*)&As[k][co0];
            ulonglong2 bp = *(const ulonglong2*)&Bs[k][n0];   // (n0,n0+1),(n0+2,n0+3)
            u64 ad0 = dup2(a4.x), ad1 = dup2(a4.y), ad2 = dup2(a4.z), ad3 = dup2(a4.w);
            fma2(acc[0][0], bp.x, ad0); fma2(acc[0][1], bp.y, ad0);
            fma2(acc[1][0], bp.x, ad1); fma2(acc[1][1], bp.y, ad1);
            fma2(acc[2][0], bp.x, ad2); fma2(acc[2][1], bp.y, ad2);
            fma2(acc[3][0], bp.x, ad3); fma2(acc[3][1], bp.y, ad3);
        }
        __syncthreads();
    }
    #pragma unroll
    for (int i = 0; i < 4; ++i) {
        int co = co0 + i;
        float sc = gamma[co] * rsqrtf(var[co] + 1e-5f);
        float sh = beta[co] - mean[co] * sc;
        float2 lo = unpack2(acc[i][0]);
        float2 hi = unpack2(acc[i][1]);
        float4 v;
        v.x = fmaxf(lo.x * sc + sh, 0.f);
        v.y = fmaxf(lo.y * sc + sh, 0.f);
        v.z = fmaxf(hi.x * sc + sh, 0.f);
        v.w = fmaxf(hi.y * sc + sh, 0.f);
        *(float4*)&g_W1[((size_t)b * CMID + co) * HWHW + n_base + n0] = v;
    }
}

// ---------------------------------------------------------------------------
// K2: 3x3 conv (64ci -> 100co, pad 1) + BN (no relu)
// block: 32x16 spatial tile, 256 thr, thread = 2 pixels (ty, ty+8) x 4 co
// co held as 2 f32x2 pairs; weights read as ulonglong2 (natural pairs)
// grid (8 tiles, 25 co-groups, 2 b); ci-chunks of 16 in smem
// ---------------------------------------------------------------------------
__global__ __launch_bounds__(256) void k2_conv3x3(
    const float* __restrict__ ew,
    const float* __restrict__ gamma, const float* __restrict__ beta,
    const float* __restrict__ mean, const float* __restrict__ var)
{
    __shared__ float Xs[16][18][36];               // [ci][row][col], 34 used
    __shared__ __align__(16) float Ws2[16][9][4];  // [ci][k][co]
    int b = blockIdx.z;
    int co0 = blockIdx.y * 4;
    int ty0 = (blockIdx.x >> 1) * 16;
    int tx0 = (blockIdx.x & 1) * 32;
    int t = threadIdx.x;
    int tx = t & 31, ty = t >> 5;                  // ty in 0..7, 2 rows/thread

    // staging thread map (fixed per thread, computed once)
    int sc_ = t >> 4;          // ci lane 0..15
    int sq  = t & 15;          // col lane 0..15 -> cols sq, sq+16, (sq+32 if sq<2)
    int xg1 = tx0 + sq - 1;
    int xg2 = tx0 + sq + 15;
    int xg3 = tx0 + sq + 31;
    bool okx1 = (xg1 >= 0) && (xg1 < 64);
    bool okx2 = (xg2 < 64);                       // xg2 >= 15 always
    bool okx3 = (sq < 2) && (xg3 < 64);

    u64 acc0[2] = {0ULL, 0ULL}, acc1[2] = {0ULL, 0ULL};
    for (int cic = 0; cic < 4; ++cic) {
        {   // X stage: rows 18, thread owns (ci=sc_, cols sq/sq+16/sq+32)
            const float* basec = g_W1 +
                (((size_t)b * CMID + cic * 16 + sc_) * 64) * 64;
            #pragma unroll 3
            for (int r = 0; r < 18; ++r) {
                int y = ty0 + r - 1;
                bool oky = (y >= 0) && (y < 64);
                const float* src = basec + (size_t)y * 64;
                float v1 = 0.f, v2 = 0.f, v3 = 0.f;
                if (oky) {
                    if (okx1) v1 = src[xg1];
                    if (okx2) v2 = src[xg2];
                    if (okx3) v3 = src[xg3];
                }
                float* dst = &Xs[sc_][r][0];
                dst[sq] = v1;
                dst[sq + 16] = v2;
                if (sq < 2) dst[sq + 32] = v3;
            }
        }
        for (int e = t; e < 576; e += 256) {
            int co = e & 3, rem = e >> 2;
            int k = rem % 9, ci = rem / 9;
            Ws2[ci][k][co] = ew[(size_t)(co0 + co) * (CMID * 9) + (cic * 16 + ci) * 9 + k];
        }
        __syncthreads();
        for (int ci = 0; ci < 16; ++ci) {
            #pragma unroll
            for (int ky = 0; ky < 3; ++ky)
            #pragma unroll
            for (int kx = 0; kx < 3; ++kx) {
                float xv0 = Xs[ci][ty + ky][tx + kx];
                float xv1 = Xs[ci][ty + 8 + ky][tx + kx];
                ulonglong2 wp = *(const ulonglong2*)&Ws2[ci][ky * 3 + kx][0];
                u64 x0d = dup2(xv0), x1d = dup2(xv1);
                fma2(acc0[0], wp.x, x0d); fma2(acc0[1], wp.y, x0d);
                fma2(acc1[0], wp.x, x1d); fma2(acc1[1], wp.y, x1d);
            }
        }
        __syncthreads();
    }
    float r0[4], r1[4];
    { float2 f = unpack2(acc0[0]); r0[0] = f.x; r0[1] = f.y; }
    { float2 f = unpack2(acc0[1]); r0[2] = f.x; r0[3] = f.y; }
    { float2 f = unpack2(acc1[0]); r1[0] = f.x; r1[1] = f.y; }
    { float2 f = unpack2(acc1[1]); r1[2] = f.x; r1[3] = f.y; }
    #pragma unroll
    for (int i = 0; i < 4; ++i) {
        int ch = co0 + i;
        float sc = gamma[ch] * rsqrtf(var[ch] + 1e-5f);
        float sh = beta[ch] - mean[ch] * sc;
        size_t base = ((size_t)b * CENC + ch) * 64;
        g_W2[(base + ty0 + ty) * 64 + tx0 + tx]     = r0[i] * sc + sh;
        g_W2[(base + ty0 + ty + 8) * 64 + tx0 + tx] = r1[i] * sc + sh;
    }
}

// ---------------------------------------------------------------------------
// K3: pixel-shuffle + clamp + pow + softmax over 25 taps (BN already in K2)
// thread = (b, pixel, dydx); writes into k4-tile-permuted g_Wn
// ---------------------------------------------------------------------------
__global__ __launch_bounds__(256) void k3_weights(const float* __restrict__ power_p)
{
    int idx = blockIdx.x * 256 + threadIdx.x;   // 32768 total
    int d = idx & 3;
    int rest = idx >> 2;                        // b*4096 + hl*64 + wl
    int pix = rest & 4095, b = rest >> 12;
    int hl = pix >> 6, wl = pix & 63;
    float p = fmaxf(power_p[0], 1e-5f);
    float v[25];
    float m = -1e30f;
    #pragma unroll
    for (int k = 0; k < 25; ++k) {
        int ch = k * 4 + d;                     // pixel-shuffle channel
        float raw = g_W2[((size_t)b * CENC + ch) * HWHW + pix];
        float x = fmaxf(raw, 1e-5f);
        x = __powf(x, p);
        v[k] = x;
        m = fmaxf(m, x);
    }
    float s = 0.f;
    #pragma unroll
    for (int k = 0; k < 25; ++k) { v[k] = __expf(v[k] - m); s += v[k]; }
    float inv = 1.f / s;
    // permuted output: [b][tile][within][k][d]
    int tile   = ((hl >> 3) << 3) + (wl >> 3);
    int within = ((hl & 7) << 3) + (wl & 7);
    float* o = g_Wn + (((size_t)b * 64 + tile) * 64 + within) * 100;
    #pragma unroll
    for (int k = 0; k < 25; ++k) o[k * 4 + d] = v[k] * inv;
}

// ---------------------------------------------------------------------------
// K4: weighted 5x5 low-res gather -> 128x128 output
// block: 8x8 low-res tile x 32 channels, 256 thr = 64 spatial x 4 ch-quads
// channel PAIRS packed as f32x2 (X LDS.128 read as ulonglong2 = 2 operands),
// weights duplicated lane-wise. Per tap: 3 LDS.128 + 4 dup + 16 FFMA2.
// grid (64 tiles, 8 ch-chunks, 2 b)
// ---------------------------------------------------------------------------
__global__ __launch_bounds__(256) void k4_gather(
    const float* __restrict__ X, float* __restrict__ out)
{
    __shared__ __align__(16) float Xs[12][12][36];  // [r][x][c], 32 ch used
    __shared__ __align__(16) float Ws[64][25][4];   // [within][tap][subpix]
    int b = blockIdx.z;
    int c0 = blockIdx.y * 32;
    int tile = blockIdx.x;
    int ty0 = (tile >> 3) * 8;
    int tx0 = (tile & 7) * 8;
    int t = threadIdx.x;
    int sp = t & 63;                 // spatial fastest (warp = 32 spatials)
    int j  = t >> 6;                 // channel quad 0..3
    int sx = sp & 7, sy = sp >> 3;

    // weights: linear copy of 1600 float4 (already in this block's order)
    {
        const float4* wg4 = (const float4*)g_Wn + ((size_t)b * 64 + tile) * 1600;
        float4* wsm = (float4*)&Ws[0][0][0];
        #pragma unroll
        for (int e = t; e < 1600; e += 256) wsm[e] = wg4[e];
    }
    // X tile: threads 0..143 own one (r,x), loop 32 channels with ptr bump
    if (t < 144) {
        int r = t / 12, x = t % 12;
        int y = ty0 + r - 2, xg = tx0 + x - 2;
        bool ok = (y >= 0) && (y < 64) && (xg >= 0) && (xg < 64);
        const float* src = X + (((size_t)b * CIN + c0) * 64 + y) * 64 + xg;
        float* dst = &Xs[r][x][0];
        #pragma unroll 4
        for (int c = 0; c < 32; ++c) {
            float v = 0.f;
            if (ok) v = src[(size_t)c * HWHW];
            dst[c] = v;
        }
    }
    __syncthreads();

    // A0[p][d]: channels (clo+2p, clo+2p+1) x subpix d ; A1 for chunk +16
    u64 A0[2][4], A1[2][4];
    #pragma unroll
    for (int p = 0; p < 2; ++p)
        #pragma unroll
        for (int dd = 0; dd < 4; ++dd) { A0[p][dd] = 0ULL; A1[p][dd] = 0ULL; }
    int clo = j * 4, chi = 16 + j * 4;
    #pragma unroll
    for (int k = 0; k < 25; ++k) {
        int ki = k / 5, kj = k % 5;
        const float4 w4 = *(const float4*)&Ws[sp][k][0];
        u64 wd0 = dup2(w4.x), wd1 = dup2(w4.y), wd2 = dup2(w4.z), wd3 = dup2(w4.w);
        ulonglong2 x0 = *(const ulonglong2*)&Xs[sy + ki][sx + kj][clo];
        ulonglong2 x1 = *(const ulonglong2*)&Xs[sy + ki][sx + kj][chi];
        fma2(A0[0][0], x0.x, wd0); fma2(A0[0][1], x0.x, wd1);
        fma2(A0[0][2], x0.x, wd2); fma2(A0[0][3], x0.x, wd3);
        fma2(A0[1][0], x0.y, wd0); fma2(A0[1][1], x0.y, wd1);
        fma2(A0[1][2], x0.y, wd2); fma2(A0[1][3], x0.y, wd3);
        fma2(A1[0][0], x1.x, wd0); fma2(A1[0][1], x1.x, wd1);
        fma2(A1[0][2], x1.x, wd2); fma2(A1[0][3], x1.x, wd3);
        fma2(A1[1][0], x1.y, wd0); fma2(A1[1][1], x1.y, wd1);
        fma2(A1[1][2], x1.y, wd2); fma2(A1[1][3], x1.y, wd3);
    }

    // unpack to per-channel subpix values, then store (float2 over dx)
    float a0[4][4], a1[4][4];
    #pragma unroll
    for (int p = 0; p < 2; ++p)
        #pragma unroll
        for (int dd = 0; dd < 4; ++dd) {
            float2 f0 = unpack2(A0[p][dd]);
            a0[2 * p][dd] = f0.x; a0[2 * p + 1][dd] = f0.y;
            float2 f1 = unpack2(A1[p][dd]);
            a1[2 * p][dd] = f1.x; a1[2 * p + 1][dd] = f1.y;
        }
    int hl = ty0 + sy, wl = tx0 + sx;
    int w_ = 2 * wl;
    #pragma unroll
    for (int i = 0; i < 4; ++i) {
        {   // chunk 0
            size_t cb = (((size_t)b * CIN + c0 + clo + i) * 128) * 128;
            *(float2*)&out[cb + (size_t)(2 * hl)     * 128 + w_] = make_float2(a0[i][0], a0[i][1]);
            *(float2*)&out[cb + (size_t)(2 * hl + 1) * 128 + w_] = make_float2(a0[i][2], a0[i][3]);
        }
        {   // chunk 1
            size_t cb = (((size_t)b * CIN + c0 + chi + i) * 128) * 128;
            *(float2*)&out[cb + (size_t)(2 * hl)     * 128 + w_] = make_float2(a1[i][0], a1[i][1]);
            *(float2*)&out[cb + (size_t)(2 * hl + 1) * 128 + w_] = make_float2(a1[i][2], a1[i][3]);
        }
    }
}

// ---------------------------------------------------------------------------
extern "C" void kernel_launch(void* const* d_in, const int* in_sizes, int n_in,
                              void* d_out, int out_size)
{
    const float* X          = (const float*)d_in[0];
    const float* comp_w     = (const float*)d_in[1];
    const float* comp_gamma = (const float*)d_in[2];
    const float* comp_beta  = (const float*)d_in[3];
    const float* comp_mean  = (const float*)d_in[4];
    const float* comp_var   = (const float*)d_in[5];
    const float* enc_w      = (const float*)d_in[6];
    const float* enc_gamma  = (const float*)d_in[7];
    const float* enc_beta   = (const float*)d_in[8];
    const float* enc_mean   = (const float*)d_in[9];
    const float* enc_var    = (const float*)d_in[10];
    const float* power_p    = (const float*)d_in[11];
    float* out = (float*)d_out;

    k1_conv1x1<<<dim3(64, 2), 256>>>(X, comp_w, comp_gamma, comp_beta,
                                     comp_mean, comp_var);
    k2_conv3x3<<<dim3(8, 25, 2), 256>>>(enc_w, enc_gamma, enc_beta,
                                        enc_mean, enc_var);
    k3_weights<<<128, 256>>>(power_p);
    k4_gather<<<dim3(64, 8, 2), 256>>>(X, out);
}

// round 12
// speedup vs baseline: 1.7934x; 1.0527x over previous
#include <cuda_runtime.h>

#define BB   2
#define CIN  256
#define CMID 64
#define CENC 100
#define HWHW 4096   // 64*64

typedef unsigned long long u64;

// ---- packed fp32x2 helpers (FFMA2: one instr = two fp32 FMAs, full precision)
__device__ __forceinline__ u64 dup2(float v) {
    u64 r; asm("mov.b64 %0, {%1,%1};" : "=l"(r) : "f"(v)); return r;
}
__device__ __forceinline__ void fma2(u64& d, u64 a, u64 b) {
    asm("fma.rn.f32x2 %0, %1, %2, %0;" : "+l"(d) : "l"(a), "l"(b));
}
__device__ __forceinline__ float2 unpack2(u64 v) {
    float2 f; asm("mov.b64 {%0,%1}, %2;" : "=f"(f.x), "=f"(f.y) : "l"(v)); return f;
}

// Scratch (allocation-free rule: __device__ globals)
__device__ float g_W1[BB * CMID * HWHW];        // conv1 output (b,64,64,64)
__device__ float g_W2[BB * CENC * HWHW];        // conv2 output (b,100,64,64)
// softmaxed weights permuted to k4's tile order: [b][tile(64)][within(64)][k(25)][d(4)]
__device__ float g_Wn[BB * 64 * 64 * 100];

// ---------------------------------------------------------------------------
// K1: 1x1 conv (GEMM M=64co x K=256ci x N=4096hw) + BN + ReLU
// block: 64co x 64n, 128 threads, thread = 8co (4 co-pairs) x 4n, k-chunk 16
// per k: 2 A LDS.128 (natural co-pairs) + 1 B LDS.128 + 4 dup + 16 FFMA2
// ---------------------------------------------------------------------------
__global__ __launch_bounds__(128) void k1_conv1x1(
    const float* __restrict__ X, const float* __restrict__ cw,
    const float* __restrict__ gamma, const float* __restrict__ beta,
    const float* __restrict__ mean, const float* __restrict__ var)
{
    __shared__ __align__(16) float As[16][68];   // [k][co]
    __shared__ __align__(16) float Bs[16][72];   // [k][n]
    int b = blockIdx.y;
    int n_base = blockIdx.x * 64;
    int t = threadIdx.x;
    int co0 = (t & 7) * 8;
    int n0  = (t >> 3) * 4;
    const float* Xb = X + (size_t)b * CIN * HWHW;
    u64 acc[4][4];                               // [co-pair][n]
    #pragma unroll
    for (int p = 0; p < 4; ++p)
        #pragma unroll
        for (int nj = 0; nj < 4; ++nj) acc[p][nj] = 0ULL;

    for (int kc = 0; kc < CIN; kc += 16) {
        {   // A: cw[co][ci] -> As[k][co]  (transpose on store)
            int co = t & 63, kk = (t >> 6) * 8;
            float4 a0 = *(const float4*)&cw[(size_t)co * CIN + kc + kk];
            float4 a1 = *(const float4*)&cw[(size_t)co * CIN + kc + kk + 4];
            As[kk + 0][co] = a0.x; As[kk + 1][co] = a0.y;
            As[kk + 2][co] = a0.z; As[kk + 3][co] = a0.w;
            As[kk + 4][co] = a1.x; As[kk + 5][co] = a1.y;
            As[kk + 6][co] = a1.z; As[kk + 7][co] = a1.w;
        }
        {   // B: X[k][n] -> Bs[k][n]
            int kk = t >> 3, nn = (t & 7) * 8;
            float4 b0 = *(const float4*)&Xb[(size_t)(kc + kk) * HWHW + n_base + nn];
            float4 b1 = *(const float4*)&Xb[(size_t)(kc + kk) * HWHW + n_base + nn + 4];
            *(float4*)&Bs[kk][nn] = b0;
            *(float4*)&Bs[kk][nn + 4] = b1;
        }
        __syncthreads();
        #pragma unroll
        for (int k = 0; k < 16; ++k) {
            ulonglong2 aLo = *(const ulonglong2*)&As[k][co0];       // pairs 0,1
            ulonglong2 aHi = *(const ulonglong2*)&As[k][co0 + 4];   // pairs 2,3
            float4 bv = *(const float4*)&Bs[k][n0];
            u64 bd0 = dup2(bv.x), bd1 = dup2(bv.y), bd2 = dup2(bv.z), bd3 = dup2(bv.w);
            fma2(acc[0][0], aLo.x, bd0); fma2(acc[0][1], aLo.x, bd1);
            fma2(acc[0][2], aLo.x, bd2); fma2(acc[0][3], aLo.x, bd3);
            fma2(acc[1][0], aLo.y, bd0); fma2(acc[1][1], aLo.y, bd1);
            fma2(acc[1][2], aLo.y, bd2); fma2(acc[1][3], aLo.y, bd3);
            fma2(acc[2][0], aHi.x, bd0); fma2(acc[2][1], aHi.x, bd1);
            fma2(acc[2][2], aHi.x, bd2); fma2(acc[2][3], aHi.x, bd3);
            fma2(acc[3][0], aHi.y, bd0); fma2(acc[3][1], aHi.y, bd1);
            fma2(acc[3][2], aHi.y, bd2); fma2(acc[3][3], aHi.y, bd3);
        }
        __syncthreads();
    }
    float val[8][4];
    #pragma unroll
    for (int p = 0; p < 4; ++p)
        #pragma unroll
        for (int nj = 0; nj < 4; ++nj) {
            float2 f = unpack2(acc[p][nj]);
            val[2 * p][nj] = f.x; val[2 * p + 1][nj] = f.y;
        }
    #pragma unroll
    for (int i = 0; i < 8; ++i) {
        int co = co0 + i;
        float sc = gamma[co] * rsqrtf(var[co] + 1e-5f);
        float sh = beta[co] - mean[co] * sc;
        float4 v;
        v.x = fmaxf(val[i][0] * sc + sh, 0.f);
        v.y = fmaxf(val[i][1] * sc + sh, 0.f);
        v.z = fmaxf(val[i][2] * sc + sh, 0.f);
        v.w = fmaxf(val[i][3] * sc + sh, 0.f);
        *(float4*)&g_W1[((size_t)b * CMID + co) * HWHW + n_base + n0] = v;
    }
}

// ---------------------------------------------------------------------------
// K2: 3x3 conv (64ci -> 100co, pad 1) + BN (no relu)
// block: 32x8 spatial tile, 128 thr = 32 cols x 4 row-lanes, thread = 2 rows
// (ty, ty+4) x 8 co (4 co-pairs). Full warp on one row -> conflict-free LDS.
// grid (16 tiles, 13 co-groups-of-8 (last ragged 4), 2 b); ci-chunks of 16.
// per (ci,k): 2 LDS.32 + 2 dup + 2 W LDS.128(bcast) + 8 FFMA2 = 32 laneFMA
// ---------------------------------------------------------------------------
__global__ __launch_bounds__(128) void k2_conv3x3(
    const float* __restrict__ ew,
    const float* __restrict__ gamma, const float* __restrict__ beta,
    const float* __restrict__ mean, const float* __restrict__ var)
{
    __shared__ float Xs[16][10][36];               // [ci][row][col], 34 used
    __shared__ __align__(16) float Ws2[16][9][8];  // [ci][k][co]
    int b = blockIdx.z;
    int co0 = blockIdx.y * 8;
    int tx0 = (blockIdx.x & 1) * 32;
    int ty0 = (blockIdx.x >> 1) * 8;
    int t = threadIdx.x;
    int tx = t & 31, ty = t >> 5;                  // ty 0..3, rows ty, ty+4

    // staging map: thread = (ci = t>>3, col lane sq = t&7): cols sq+8m, m=0..4
    int sc_ = t >> 3;
    int sq  = t & 7;
    int xg[5]; bool okx[5];
    #pragma unroll
    for (int m = 0; m < 5; ++m) {
        int col = sq + 8 * m;
        xg[m] = tx0 + col - 1;
        okx[m] = (col < 34) && (xg[m] >= 0) && (xg[m] < 64);
    }

    u64 acc0[4] = {0ULL, 0ULL, 0ULL, 0ULL};
    u64 acc1[4] = {0ULL, 0ULL, 0ULL, 0ULL};
    for (int cic = 0; cic < 4; ++cic) {
        {   // X stage: 10 rows
            const float* basec = g_W1 +
                (((size_t)b * CMID + cic * 16 + sc_) * 64) * 64;
            #pragma unroll 2
            for (int r = 0; r < 10; ++r) {
                int y = ty0 + r - 1;
                bool oky = (y >= 0) && (y < 64);
                const float* src = basec + (size_t)y * 64;
                float* dst = &Xs[sc_][r][0];
                #pragma unroll
                for (int m = 0; m < 5; ++m) {
                    int col = sq + 8 * m;
                    float v = (oky && okx[m]) ? src[xg[m]] : 0.f;
                    if (col < 34) dst[col] = v;
                }
            }
        }
        // W stage: 16ci x 9k x 8co = 1152, guard ragged co
        for (int e = t; e < 1152; e += 128) {
            int co = e & 7, rem = e >> 3;
            int k = rem % 9, ci = rem / 9;
            int cg = co0 + co;
            float w = (cg < CENC)
                ? ew[(size_t)cg * (CMID * 9) + (cic * 16 + ci) * 9 + k] : 0.f;
            Ws2[ci][k][co] = w;
        }
        __syncthreads();
        for (int ci = 0; ci < 16; ++ci) {
            #pragma unroll
            for (int ky = 0; ky < 3; ++ky)
            #pragma unroll
            for (int kx = 0; kx < 3; ++kx) {
                float xv0 = Xs[ci][ty + ky][tx + kx];
                float xv1 = Xs[ci][ty + 4 + ky][tx + kx];
                ulonglong2 wLo = *(const ulonglong2*)&Ws2[ci][ky * 3 + kx][0];
                ulonglong2 wHi = *(const ulonglong2*)&Ws2[ci][ky * 3 + kx][4];
                u64 x0d = dup2(xv0), x1d = dup2(xv1);
                fma2(acc0[0], wLo.x, x0d); fma2(acc0[1], wLo.y, x0d);
                fma2(acc0[2], wHi.x, x0d); fma2(acc0[3], wHi.y, x0d);
                fma2(acc1[0], wLo.x, x1d); fma2(acc1[1], wLo.y, x1d);
                fma2(acc1[2], wHi.x, x1d); fma2(acc1[3], wHi.y, x1d);
            }
        }
        __syncthreads();
    }
    float r0[8], r1[8];
    #pragma unroll
    for (int q = 0; q < 4; ++q) {
        float2 f0 = unpack2(acc0[q]); r0[2 * q] = f0.x; r0[2 * q + 1] = f0.y;
        float2 f1 = unpack2(acc1[q]); r1[2 * q] = f1.x; r1[2 * q + 1] = f1.y;
    }
    #pragma unroll
    for (int i = 0; i < 8; ++i) {
        int ch = co0 + i;
        if (ch < CENC) {
            float sc = gamma[ch] * rsqrtf(var[ch] + 1e-5f);
            float sh = beta[ch] - mean[ch] * sc;
            size_t base = ((size_t)b * CENC + ch) * 64;
            g_W2[(base + ty0 + ty) * 64 + tx0 + tx]     = r0[i] * sc + sh;
            g_W2[(base + ty0 + ty + 4) * 64 + tx0 + tx] = r1[i] * sc + sh;
        }
    }
}

// ---------------------------------------------------------------------------
// K3: pixel-shuffle + clamp + pow + softmax over 25 taps (BN already in K2)
// thread = (b, pixel, dydx); writes into k4-tile-permuted g_Wn
// ---------------------------------------------------------------------------
__global__ __launch_bounds__(256) void k3_weights(const float* __restrict__ power_p)
{
    int idx = blockIdx.x * 256 + threadIdx.x;   // 32768 total
    int d = idx & 3;
    int rest = idx >> 2;                        // b*4096 + hl*64 + wl
    int pix = rest & 4095, b = rest >> 12;
    int hl = pix >> 6, wl = pix & 63;
    float p = fmaxf(power_p[0], 1e-5f);
    float v[25];
    float m = -1e30f;
    #pragma unroll
    for (int k = 0; k < 25; ++k) {
        int ch = k * 4 + d;                     // pixel-shuffle channel
        float raw = g_W2[((size_t)b * CENC + ch) * HWHW + pix];
        float x = fmaxf(raw, 1e-5f);
        x = __powf(x, p);
        v[k] = x;
        m = fmaxf(m, x);
    }
    float s = 0.f;
    #pragma unroll
    for (int k = 0; k < 25; ++k) { v[k] = __expf(v[k] - m); s += v[k]; }
    float inv = 1.f / s;
    // permuted output: [b][tile][within][k][d]
    int tile   = ((hl >> 3) << 3) + (wl >> 3);
    int within = ((hl & 7) << 3) + (wl & 7);
    float* o = g_Wn + (((size_t)b * 64 + tile) * 64 + within) * 100;
    #pragma unroll
    for (int k = 0; k < 25; ++k) o[k * 4 + d] = v[k] * inv;
}

// ---------------------------------------------------------------------------
// K4: weighted 5x5 low-res gather -> 128x128 output
// block: 8x8 low-res tile x 32 channels, 128 thr = 64 spatial x 2 halves,
// thread = 16 channels x 4 subpixels.
// per tap: 1 W LDS.128 + 4 X LDS.128 (80B) + 4 dup + 32 FFMA2 = 64 laneFMA
// -> 1.25 B LDS per lane-FMA (was 1.5) and 2x ILP per load batch.
// grid (64 tiles, 8 ch-chunks-of-32, 2 b)
// ---------------------------------------------------------------------------
__global__ __launch_bounds__(128) void k4_gather(
    const float* __restrict__ X, float* __restrict__ out)
{
    __shared__ __align__(16) float Xs[12][12][36];  // [r][x][c], 32 ch
    __shared__ __align__(16) float Ws[64][25][4];   // [within][tap][subpix]
    int b = blockIdx.z;
    int c0 = blockIdx.y * 32;
    int tile = blockIdx.x;
    int ty0 = (tile >> 3) * 8;
    int tx0 = (tile & 7) * 8;
    int t = threadIdx.x;
    int sp = t & 63;                 // spatial (warp = 32 spatials)
    int j  = t >> 6;                 // channel half 0..1 (16 ch each)
    int sx = sp & 7, sy = sp >> 3;

    // weights: linear copy of 1600 float4 (already in this block's order)
    {
        const float4* wg4 = (const float4*)g_Wn + ((size_t)b * 64 + tile) * 1600;
        float4* wsm = (float4*)&Ws[0][0][0];
        for (int e = t; e < 1600; e += 128) wsm[e] = wg4[e];
    }
    // X tile: positions own a fixed (r,x); pack 4 channels -> STS.128
    for (int pos = t; pos < 144; pos += 128) {
        int r = pos / 12, x = pos % 12;
        int y = ty0 + r - 2, xg = tx0 + x - 2;
        bool ok = (y >= 0) && (y < 64) && (xg >= 0) && (xg < 64);
        const float* src = X + (((size_t)b * CIN + c0) * 64 + y) * 64 + xg;
        float* dst = &Xs[r][x][0];
        #pragma unroll
        for (int c = 0; c < 32; c += 4) {
            float4 v;
            v.x = ok ? src[(size_t)(c + 0) * HWHW] : 0.f;
            v.y = ok ? src[(size_t)(c + 1) * HWHW] : 0.f;
            v.z = ok ? src[(size_t)(c + 2) * HWHW] : 0.f;
            v.w = ok ? src[(size_t)(c + 3) * HWHW] : 0.f;
            *(float4*)&dst[c] = v;
        }
    }
    __syncthreads();

    // acc[pp][dd]: channel pair pp (ch 2pp,2pp+1 of this half) x subpix dd
    u64 acc[8][4];
    #pragma unroll
    for (int pp = 0; pp < 8; ++pp)
        #pragma unroll
        for (int dd = 0; dd < 4; ++dd) acc[pp][dd] = 0ULL;
    int cb16 = j * 16;
    #pragma unroll
    for (int k = 0; k < 25; ++k) {
        int ki = k / 5, kj = k % 5;
        const float4 w4 = *(const float4*)&Ws[sp][k][0];
        u64 wd0 = dup2(w4.x), wd1 = dup2(w4.y), wd2 = dup2(w4.z), wd3 = dup2(w4.w);
        const float* xr = &Xs[sy + ki][sx + kj][cb16];
        ulonglong2 xa = *(const ulonglong2*)&xr[0];
        ulonglong2 xb = *(const ulonglong2*)&xr[4];
        ulonglong2 xc = *(const ulonglong2*)&xr[8];
        ulonglong2 xd = *(const ulonglong2*)&xr[12];
        u64 xp[8] = {xa.x, xa.y, xb.x, xb.y, xc.x, xc.y, xd.x, xd.y};
        #pragma unroll
        for (int pp = 0; pp < 8; ++pp) {
            fma2(acc[pp][0], xp[pp], wd0);
            fma2(acc[pp][1], xp[pp], wd1);
            fma2(acc[pp][2], xp[pp], wd2);
            fma2(acc[pp][3], xp[pp], wd3);
        }
    }

    // unpack + store: subpix d = dy*2+dx ; float2 over dx
    int hl = ty0 + sy, wl = tx0 + sx;
    int w_ = 2 * wl;
    #pragma unroll
    for (int pp = 0; pp < 8; ++pp) {
        float a[2][4];
        #pragma unroll
        for (int dd = 0; dd < 4; ++dd) {
            float2 f = unpack2(acc[pp][dd]);
            a[0][dd] = f.x; a[1][dd] = f.y;
        }
        #pragma unroll
        for (int q = 0; q < 2; ++q) {
            int ch = c0 + cb16 + 2 * pp + q;
            size_t cbase = (((size_t)b * CIN + ch) * 128) * 128;
            *(float2*)&out[cbase + (size_t)(2 * hl)     * 128 + w_] = make_float2(a[q][0], a[q][1]);
            *(float2*)&out[cbase + (size_t)(2 * hl + 1) * 128 + w_] = make_float2(a[q][2], a[q][3]);
        }
    }
}

// ---------------------------------------------------------------------------
extern "C" void kernel_launch(void* const* d_in, const int* in_sizes, int n_in,
                              void* d_out, int out_size)
{
    const float* X          = (const float*)d_in[0];
    const float* comp_w     = (const float*)d_in[1];
    const float* comp_gamma = (const float*)d_in[2];
    const float* comp_beta  = (const float*)d_in[3];
    const float* comp_mean  = (const float*)d_in[4];
    const float* comp_var   = (const float*)d_in[5];
    const float* enc_w      = (const float*)d_in[6];
    const float* enc_gamma  = (const float*)d_in[7];
    const float* enc_beta   = (const float*)d_in[8];
    const float* enc_mean   = (const float*)d_in[9];
    const float* enc_var    = (const float*)d_in[10];
    const float* power_p    = (const float*)d_in[11];
    float* out = (float*)d_out;

    k1_conv1x1<<<dim3(64, 2), 128>>>(X, comp_w, comp_gamma, comp_beta,
                                     comp_mean, comp_var);
    k2_conv3x3<<<dim3(16, 13, 2), 128>>>(enc_w, enc_gamma, enc_beta,
                                         enc_mean, enc_var);
    k3_weights<<<128, 256>>>(power_p);
    k4_gather<<<dim3(64, 8, 2), 128>>>(X, out);
}